// round 15
// baseline (speedup 1.0000x reference)
#include <cuda_runtime.h>
#include <cuda_fp16.h>
#include <cstdint>
#include <cstddef>

// Problem constants: B=4, S=4096 -> N=16384 tokens
#define N_TOK 16384
#define DIM   4096
#define OUT_D 4096
#define SCALING 0.5f
#define W1_N8 18   // 144 rows / 8: 16 A-blocks + router-hi + router-lo

// -------- static scratch, fp16 fragment-major (m16n8k16) --------
// GEMM1 B operand, interleaved per k32: [k32 0..127][n8 0..17][lane][4]
__device__ __align__(16) uint32_t g_w1f[128 * W1_N8 * 128];
// GEMM2 B operand: [n8 0..511][k16 0..7][lane*2 + reg]
__device__ __align__(16) uint32_t g_btf[512 * 8 * 64];
// GEMM2 A operand: [m16 0..1023][k16 0..7][lane*4 + reg]
__device__ __align__(16) uint32_t g_hwf[(size_t)1024 * 8 * 128];

// -------- helpers --------
__device__ __forceinline__ uint32_t pack_f16x2(float lo, float hi) {
    uint32_t r;   // d.low = 2nd src, d.high = 1st src
    asm("cvt.rn.f16x2.f32 %0, %1, %2;" : "=r"(r) : "f"(hi), "f"(lo));
    return r;
}
__device__ __forceinline__ float2 unpack_f16x2(uint32_t v) {
    __half2 h = *(__half2*)&v;
    return __half22float2(h);
}
__device__ __forceinline__ void mma_f16(float* c, const uint32_t* a,
                                        uint32_t b0, uint32_t b1) {
    asm volatile(
        "mma.sync.aligned.m16n8k16.row.col.f32.f16.f16.f32 "
        "{%0,%1,%2,%3}, {%4,%5,%6,%7}, {%8,%9}, {%0,%1,%2,%3};\n"
        : "+f"(c[0]), "+f"(c[1]), "+f"(c[2]), "+f"(c[3])
        : "r"(a[0]), "r"(a[1]), "r"(a[2]), "r"(a[3]), "r"(b0), "r"(b1));
}
__device__ __forceinline__ void cp16(void* dst, const void* src) {
    uint32_t d = (uint32_t)__cvta_generic_to_shared(dst);
    asm volatile("cp.async.cg.shared.global [%0], [%1], 16;" :: "r"(d), "l"(src));
}
#define CP_COMMIT() asm volatile("cp.async.commit_group;")
#define CP_WAIT(n)  asm volatile("cp.async.wait_group %0;" :: "n"(n))

// ============================================================================
// Prep: build fp16 fragment-major operand tensors once. (unchanged from R14)
// ============================================================================
__global__ void prep_kernel(const float* __restrict__ rw,
                            const float* __restrict__ A,
                            const float* __restrict__ Bm)
{
    const int nthr = gridDim.x * blockDim.x;
    const int tid0 = blockIdx.x * blockDim.x + threadIdx.x;
    for (int i = tid0; i < 144 * 2048; i += nthr) {
        int n = i >> 11, k = (i & 2047) * 2;
        float v0, v1;
        if (n < 128) {
            v0 = A[n * 4096 + k]; v1 = A[n * 4096 + k + 1];
        } else if (n < 136) {
            v0 = rw[(n - 128) * 4096 + k]; v1 = rw[(n - 128) * 4096 + k + 1];
        } else {
            float f0 = rw[(n - 136) * 4096 + k];
            float f1 = rw[(n - 136) * 4096 + k + 1];
            v0 = f0 - __half2float(__float2half_rn(f0));
            v1 = f1 - __half2float(__float2half_rn(f1));
        }
        int lane = (n & 7) * 4 + ((k & 7) >> 1);
        int idx = ((k >> 5) * W1_N8 + (n >> 3)) * 128
                + lane * 4 + ((k >> 4) & 1) * 2 + ((k >> 3) & 1);
        g_w1f[idx] = pack_f16x2(v0, v1);
    }
    for (int i = tid0; i < 4096 * 64; i += nthr) {
        int o = i >> 6, c = (i & 63) * 2;
        int e = c >> 4, r = c & 15;
        const float* bp = Bm + ((size_t)e * 4096 + o) * 16 + r;
        int idx = ((o >> 3) * 8 + (c >> 4)) * 64
                + ((o & 7) * 4 + ((c & 7) >> 1)) * 2 + ((c >> 3) & 1);
        g_btf[idx] = pack_f16x2(bp[0] * SCALING, bp[1] * SCALING);
    }
}

// ============================================================================
// GEMM1: producer/consumer split. Producer: LDG x -> pack fp16 hi+lo planes
// in A-fragment order (lane-XOR swizzle) -> STS ring-3. Consumer inner loop:
// LDS.128 A-frags + LDS.128 B-frags + MMA only. Bitwise-identical math.
// Stage = k64. One syncthreads + one CP_WAIT per stage (64 total).
// ============================================================================
#define AH_STAGE 8192                     // per stage: hi 4096 + lo 4096 words
#define A_RING   (3 * AH_STAGE)           // 24576 words (96 KB)
#define WT_WORDS (W1_N8 * 128)            // 2304 words per k32
#define WS_STAGE (2 * WT_WORDS)           // 4608
#define W_RING   (3 * WS_STAGE)           // 13824 words (54 KB)
#define SM1_WORDS (A_RING + W_RING + 1024 + 1024)   // 40448 words = 158 KB

__global__ __launch_bounds__(256, 1)
void gemm1_kernel(const float* __restrict__ x, const float* __restrict__ rb)
{
    extern __shared__ uint32_t smu[];
    uint32_t* Ar   = smu;                         // ring-3 A stages (hi+lo)
    uint32_t* Wr   = smu + A_RING;                // ring-3 W stages
    float*    gw   = (float*)(smu + A_RING + W_RING);          // [128][8]
    float*    lbuf = (float*)(smu + A_RING + W_RING + 1024);   // [8][32][4]

    const int tid  = threadIdx.x;
    const int lane = tid & 31;
    const int warp = tid >> 5;
    const int wm   = warp & 3;
    const int wn   = warp >> 2;
    const int g    = lane >> 2;
    const int tig  = lane & 3;
    const int m0   = blockIdx.x * 128;
    const int ncol0 = wn * 64;
    const int sl   = ((lane ^ ((lane >> 3) & 3)) << 2);   // consumer slot*4

    float acc[2][9][4];
#pragma unroll
    for (int mt = 0; mt < 2; mt++)
#pragma unroll
        for (int nt = 0; nt < 9; nt++)
#pragma unroll
            for (int i = 0; i < 4; i++) acc[mt][nt][i] = 0.f;

    // ---- producer helpers ----
    auto ldgStage = [&](int u, float4* v) {
        const int k0 = u * 64;
#pragma unroll
        for (int sub = 0; sub < 2; ++sub)
#pragma unroll
            for (int i = 0; i < 4; ++i) {
                int idx = tid + i * 256, row = idx >> 3, c4 = idx & 7;
                v[sub * 4 + i] = *(const float4*)(x + (size_t)(m0 + row) * DIM
                                                  + k0 + sub * 32 + 4 * c4);
            }
    };
    auto stsStage = [&](int u, const float4* v) {
        uint32_t* base = Ar + (u % 3) * AH_STAGE;
#pragma unroll
        for (int sub = 0; sub < 2; ++sub)
#pragma unroll
            for (int i = 0; i < 4; ++i) {
                int idx = tid + i * 256, row = idx >> 3, c4 = idx & 7;
                int block = (c4 >> 2) * 8 + (row >> 4);
                int Lf  = (row & 7) * 4 + (c4 & 1) * 2;
                int reg = ((row >> 3) & 1) + 2 * ((c4 >> 1) & 1);
                float4 val = v[sub * 4 + i];
                uint32_t h0 = pack_f16x2(val.x, val.y);
                uint32_t h1 = pack_f16x2(val.z, val.w);
                float2 f0 = unpack_f16x2(h0), f1 = unpack_f16x2(h1);
                uint32_t l0 = pack_f16x2(val.x - f0.x, val.y - f0.y);
                uint32_t l1 = pack_f16x2(val.z - f1.x, val.w - f1.y);
                int s0 = ((Lf       ^ ((Lf >> 3) & 3)) << 2) + reg;
                int s1 = (((Lf + 1) ^ (((Lf + 1) >> 3) & 3)) << 2) + reg;
                uint32_t* bp = base + sub * 2048 + block * 128;
                bp[s0] = h0;        bp[s1] = h1;
                bp[s0 + 4096] = l0; bp[s1 + 4096] = l1;
            }
    };
    auto issueW = [&](int u) {
        uint32_t* wdst = Wr + (u % 3) * WS_STAGE;
        const size_t src = (size_t)u * WS_STAGE;
#pragma unroll
        for (int i = 0; i < 5; ++i) {
            int idx = tid + i * 256;
            if (idx < 1152) cp16(wdst + idx * 4, g_w1f + src + idx * 4);
        }
    };

    // ---- prologue: A stages 0,1 (direct) + W groups 0,1 ----
    {
        float4 v[8];
        ldgStage(0, v); stsStage(0, v);
        ldgStage(1, v); stsStage(1, v);
    }
    issueW(0); CP_COMMIT();
    issueW(1); CP_COMMIT();

    const int U = DIM / 64;   // 64 stages
    for (int u = 0; u < U; ++u) {
        float4 v[8];
        const bool pf = (u + 2 < U);
        if (pf) ldgStage(u + 2, v);          // LDG early: latency under compute
        CP_WAIT(1);                          // W(u) landed
        __syncthreads();                     // publish A(u)/W(u); retire reads of u-1
        if (pf) issueW(u + 2);
        CP_COMMIT();                         // one group per iteration

#pragma unroll
        for (int sub = 0; sub < 2; ++sub) {
            const uint32_t* ah = Ar + (u % 3) * AH_STAGE + sub * 2048;
            const uint32_t* w  = Wr + (u % 3) * WS_STAGE + sub * WT_WORDS;
            const bool do_logits = (wn == sub);   // (2u+sub)&1 == sub

            uint4 bb4[8];
#pragma unroll
            for (int nt = 0; nt < 8; ++nt)
                bb4[nt] = *(const uint4*)(w + (wn * 8 + nt) * 128 + lane * 4);
            uint4 bh4 = make_uint4(0, 0, 0, 0), bl4 = make_uint4(0, 0, 0, 0);
            if (do_logits) {
                bh4 = *(const uint4*)(w + 16 * 128 + lane * 4);
                bl4 = *(const uint4*)(w + 17 * 128 + lane * 4);
            }

#pragma unroll
            for (int ks = 0; ks < 2; ++ks) {
                uint4 af[2];
#pragma unroll
                for (int mt = 0; mt < 2; ++mt)
                    af[mt] = *(const uint4*)(ah + (ks * 8 + wm * 2 + mt) * 128 + sl);
#pragma unroll
                for (int nt = 0; nt < 8; ++nt) {
                    uint32_t b0 = ks ? bb4[nt].z : bb4[nt].x;
                    uint32_t b1 = ks ? bb4[nt].w : bb4[nt].y;
                    mma_f16(acc[0][nt], (const uint32_t*)&af[0], b0, b1);
                    mma_f16(acc[1][nt], (const uint32_t*)&af[1], b0, b1);
                }
                if (do_logits) {
                    uint4 al[2];
#pragma unroll
                    for (int mt = 0; mt < 2; ++mt)
                        al[mt] = *(const uint4*)(ah + 4096 + (ks * 8 + wm * 2 + mt) * 128 + sl);
                    uint32_t h0 = ks ? bh4.z : bh4.x, h1 = ks ? bh4.w : bh4.y;
                    uint32_t l0 = ks ? bl4.z : bl4.x, l1 = ks ? bl4.w : bl4.y;
                    mma_f16(acc[0][8], (const uint32_t*)&af[0], h0, h1);
                    mma_f16(acc[1][8], (const uint32_t*)&af[1], h0, h1);
                    mma_f16(acc[0][8], (const uint32_t*)&af[0], l0, l1);
                    mma_f16(acc[1][8], (const uint32_t*)&af[1], l0, l1);
                    mma_f16(acc[0][8], (const uint32_t*)&al[0], h0, h1);
                    mma_f16(acc[1][8], (const uint32_t*)&al[1], h0, h1);
                }
            }
        }

        if (pf) stsStage(u + 2, v);          // write buffer (u+2)%3 (safe: != u%3)
    }

    // ---- combine partial logits: wn0 -> SMEM, wn1 adds ----
    if (wn == 0) {
#pragma unroll
        for (int mt = 0; mt < 2; ++mt)
#pragma unroll
            for (int j = 0; j < 4; ++j)
                lbuf[((wm * 2 + mt) * 32 + lane) * 4 + j] = acc[mt][8][j];
    }
    __syncthreads();

    if (wn == 1) {
        const float rb0 = rb[2 * tig];
        const float rb1 = rb[2 * tig + 1];
#pragma unroll
        for (int mt = 0; mt < 2; ++mt) {
#pragma unroll
            for (int j = 0; j < 4; ++j)
                acc[mt][8][j] += lbuf[((wm * 2 + mt) * 32 + lane) * 4 + j];
#pragma unroll
            for (int half = 0; half < 2; ++half) {
                float l0 = acc[mt][8][half * 2 + 0] + rb0;
                float l1 = acc[mt][8][half * 2 + 1] + rb1;
                float m1, m2; int i1, i2;
                if (l0 >= l1) { m1 = l0; i1 = 2 * tig;     m2 = l1; i2 = 2 * tig + 1; }
                else          { m1 = l1; i1 = 2 * tig + 1; m2 = l0; i2 = 2 * tig; }
#pragma unroll
                for (int d = 1; d <= 2; d <<= 1) {
                    float om1 = __shfl_xor_sync(0xffffffffu, m1, d);
                    int   oi1 = __shfl_xor_sync(0xffffffffu, i1, d);
                    float om2 = __shfl_xor_sync(0xffffffffu, m2, d);
                    int   oi2 = __shfl_xor_sync(0xffffffffu, i2, d);
                    if (om1 > m1) {
                        if (m1 >= om2) { m2 = m1; i2 = i1; }
                        else           { m2 = om2; i2 = oi2; }
                        m1 = om1; i1 = oi1;
                    } else if (om1 > m2) { m2 = om1; i2 = oi1; }
                }
                float g1 = 1.f / (1.f + __expf(m2 - m1));
                float g2 = 1.f - g1;
                int row = wm * 32 + mt * 16 + half * 8 + g;
                gw[row * 8 + 2 * tig]     = (2 * tig     == i1) ? g1 : ((2 * tig     == i2) ? g2 : 0.f);
                gw[row * 8 + 2 * tig + 1] = (2 * tig + 1 == i1) ? g1 : ((2 * tig + 1 == i2) ? g2 : 0.f);
            }
        }
    }
    __syncthreads();

    // ---- gate h, pack fp16, store in GEMM2 A-fragment order ----
#pragma unroll
    for (int mt = 0; mt < 2; ++mt) {
#pragma unroll
        for (int nt = 0; nt < 8; ++nt) {
            const int col = ncol0 + nt * 8 + 2 * tig;
            const int e  = col >> 4;
            const int ra = wm * 32 + mt * 16 + g;
            const float wa = gw[ra * 8 + e];
            const float wb = gw[(ra + 8) * 8 + e];
            uint32_t w0 = pack_f16x2(acc[mt][nt][0] * wa, acc[mt][nt][1] * wa);
            uint32_t w1 = pack_f16x2(acc[mt][nt][2] * wb, acc[mt][nt][3] * wb);
            const int m16 = (m0 + wm * 32 + mt * 16) >> 4;
            const int k16 = wn * 4 + (nt >> 1);
            *(uint2*)(g_hwf + ((size_t)m16 * 8 + k16) * 128
                            + lane * 4 + 2 * (nt & 1)) = make_uint2(w0, w1);
        }
    }
}

// ============================================================================
// GEMM2: persistent grid-148 over 2048 pair-tiles. (unchanged from R14)
// ============================================================================
#define BS2_WORDS 8192
#define AP2_WORDS 16384
#define SM2_WORDS (BS2_WORDS + 2 * AP2_WORDS)
#define NPAIRS2   2048
#define GRID2     148

__global__ __launch_bounds__(256, 1)
void gemm2_kernel(float* __restrict__ out)
{
    extern __shared__ uint32_t smu[];
    uint32_t* Bs = smu;
    uint32_t* As = smu + BS2_WORDS;

    const int tid  = threadIdx.x;
    const int lane = tid & 31;
    const int warp = tid >> 5;
    const int wm   = warp & 3;
    const int wn   = warp >> 2;

    auto issueA = [&](int buf, int pt) {
        const size_t src = (size_t)(pt & 63) * 2 * 8192;
        uint32_t* dst = As + buf * AP2_WORDS;
#pragma unroll
        for (int i = 0; i < 16; i++) {
            int idx = tid + i * 256;
            cp16(dst + idx * 4, g_hwf + src + idx * 4);
        }
    };

    int p0 = (int)(((long long)blockIdx.x * NPAIRS2) / GRID2);
    const int p1 = (int)(((long long)(blockIdx.x + 1) * NPAIRS2) / GRID2);

    while (p0 < p1) {
        const int nb   = p0 >> 6;
        const int send = min(p1, (nb + 1) << 6);
        const int npl  = send - p0;
        const int n0   = nb * 128;

        __syncthreads();

        {
            const size_t bo = (size_t)nb * 8192;
#pragma unroll
            for (int i = 0; i < 8; i++) {
                int idx = tid + i * 256;
                cp16(Bs + idx * 4, g_btf + bo + idx * 4);
            }
        }
        issueA(0, p0);
        CP_COMMIT();
        if (npl > 1) issueA(1, p0 + 1);
        CP_COMMIT();

        for (int i = 0; i < npl; ++i) {
            const int pt = p0 + i;
            CP_WAIT(1);
            __syncthreads();

            const uint32_t* a0 = As + (i & 1) * AP2_WORDS;
            const uint32_t* a1 = a0 + 8192;

            float acc[4][8][4];
#pragma unroll
            for (int q = 0; q < 4; q++)
#pragma unroll
                for (int nt = 0; nt < 8; nt++)
#pragma unroll
                    for (int j = 0; j < 4; j++) acc[q][nt][j] = 0.f;

#pragma unroll
            for (int ks = 0; ks < 8; ++ks) {
                uint4 af[4];
#pragma unroll
                for (int mt = 0; mt < 2; mt++) {
                    af[mt]     = *(const uint4*)(a0 + ((wm * 2 + mt) * 8 + ks) * 128 + lane * 4);
                    af[2 + mt] = *(const uint4*)(a1 + ((wm * 2 + mt) * 8 + ks) * 128 + lane * 4);
                }
                uint2 bf[8];
#pragma unroll
                for (int nt = 0; nt < 8; nt++) {
                    const int n8l = wn * 8 + nt;
                    bf[nt] = *(const uint2*)(Bs + (n8l * 8 + ks) * 64 + lane * 2);
                }
#pragma unroll
                for (int nt = 0; nt < 8; nt++)
#pragma unroll
                    for (int q = 0; q < 4; q++)
                        mma_f16(acc[q][nt], (const uint32_t*)&af[q], bf[nt].x, bf[nt].y);
            }

            {
                const int g   = lane >> 2;
                const int tig = lane & 3;
#pragma unroll
                for (int tile = 0; tile < 2; ++tile) {
                    const int mbase = ((pt & 63) * 2 + tile) * 128;
#pragma unroll
                    for (int mt = 0; mt < 2; ++mt) {
#pragma unroll
                        for (int nt = 0; nt < 8; ++nt) {
                            const int col = n0 + wn * 64 + nt * 8 + 2 * tig;
                            const int ra  = mbase + wm * 32 + mt * 16 + g;
                            const float* av = acc[tile * 2 + mt][nt];
                            *(float2*)(out + (size_t)ra * OUT_D + col) =
                                make_float2(av[0], av[1]);
                            *(float2*)(out + (size_t)(ra + 8) * OUT_D + col) =
                                make_float2(av[2], av[3]);
                        }
                    }
                }
            }

            __syncthreads();
            if (i + 2 < npl) issueA(i & 1, pt + 2);
            CP_COMMIT();
        }
        p0 = send;
    }
}

// ============================================================================
extern "C" void kernel_launch(void* const* d_in, const int* in_sizes, int n_in,
                              void* d_out, int out_size)
{
    const float* x  = (const float*)d_in[0];   // [N, 4096]
    const float* rw = (const float*)d_in[1];   // [8, 4096]
    const float* rb = (const float*)d_in[2];   // [8]
    const float* A  = (const float*)d_in[3];   // [8,16,4096]
    const float* Bm = (const float*)d_in[4];   // [8,4096,16]
    float* out = (float*)d_out;                // [N, 4096] fp32

    const int sm1 = SM1_WORDS * 4;   // 161792 B
    const int sm2 = SM2_WORDS * 4;   // 163840 B
    cudaFuncSetAttribute(gemm1_kernel,
                         cudaFuncAttributeMaxDynamicSharedMemorySize, sm1);
    cudaFuncSetAttribute(gemm2_kernel,
                         cudaFuncAttributeMaxDynamicSharedMemorySize, sm2);

    prep_kernel<<<1024, 256>>>(rw, A, Bm);
    gemm1_kernel<<<N_TOK / 128, 256, sm1>>>(x, rb);
    gemm2_kernel<<<GRID2, 256, sm2>>>(out);
}